// round 3
// baseline (speedup 1.0000x reference)
#include <cuda_runtime.h>
#include <cuda_bf16.h>
#include <math.h>

// Problem constants
#define B_  2
#define S_  2048
#define H_  1024
#define NH_ 16
#define D_  64
#define ROWS_ (B_*S_)        // 4096
#define EPS_ 1.1920929e-07f

// ---------------- scratch -------------------------------------------------------------
__device__ float g_qkv[(size_t)ROWS_ * 3 * H_];
__device__ float g_q[(size_t)B_*NH_*S_*D_];
__device__ float g_k[(size_t)B_*NH_*S_*D_];
__device__ float g_v[(size_t)B_*NH_*S_*D_];
__device__ float g_attn[(size_t)ROWS_ * H_];
__device__ float g_cos[S_*32];
__device__ float g_sin[S_*32];

// ---------------- helpers -------------------------------------------------------------
__device__ __forceinline__ unsigned f2tf32(float f) {
    unsigned u;
    asm("cvt.rna.tf32.f32 %0, %1;" : "=r"(u) : "f"(f));
    return u;
}
__device__ __forceinline__ void mma_tf32(float c[4], const unsigned a[4], const unsigned b[2]) {
    asm volatile(
        "mma.sync.aligned.m16n8k8.row.col.f32.tf32.tf32.f32 "
        "{%0,%1,%2,%3}, {%4,%5,%6,%7}, {%8,%9}, {%0,%1,%2,%3};"
        : "+f"(c[0]), "+f"(c[1]), "+f"(c[2]), "+f"(c[3])
        : "r"(a[0]), "r"(a[1]), "r"(a[2]), "r"(a[3]), "r"(b[0]), "r"(b[1]));
}

// ---------------- RoPE table ----------------------------------------------------------
__global__ void rope_table_kernel() {
    int idx = blockIdx.x * blockDim.x + threadIdx.x;
    if (idx >= S_*32) return;
    int s = idx >> 5, j = idx & 31;
    double invf = pow(1.0e-4, (double)j / 32.0);
    float f = (float)s * (float)invf;
    double sn, cs;
    sincos((double)f, &sn, &cs);
    g_cos[idx] = (float)cs;
    g_sin[idx] = (float)sn;
}

// ---------------- tf32 GEMM v2: C[M,N] = A[M,K] * B[N,K]^T ----------------------------
// 128x128 tile, BK=16, 256 thr = 8 warps (4m x 2n), warp tile 32x64.
// Pair-permuted k layout (k, k+4 adjacent), row stride 40 (==8 mod 32): LDS.64 frags
// conflict-free. Double-buffered smem + register-staged gmem prefetch, 1 sync / slab.
#define GSTR 40
#define GEMM_SMEM_BYTES (4*128*GSTR*4)   // 2 mats x 2 stages

__global__ __launch_bounds__(256)
void gemm_v2(const float* __restrict__ A, const float* __restrict__ Bm,
             float* __restrict__ C, int M, int N, int K) {
    extern __shared__ unsigned smg[];
    unsigned* As = smg;                      // [2][128][GSTR]
    unsigned* Bs = smg + 2*128*GSTR;

    const int tid  = threadIdx.x;
    const int lane = tid & 31;
    const int wid  = tid >> 5;
    const int gr   = lane >> 2;
    const int gc   = lane & 3;
    const int bm = blockIdx.y * 128;
    const int bn = blockIdx.x * 128;
    const int wm = (wid >> 1) * 32;
    const int wn = (wid & 1) * 64;

    const int lrow = tid >> 1;               // 0..127
    const int lg   = tid & 1;                // k-subgroup
    const float* Ag = A  + (size_t)(bm + lrow) * K + lg*8;
    const float* Bg = Bm + (size_t)(bn + lrow) * K + lg*8;

    float4 ra0, ra1, rb0, rb1;
    float acc[2][8][4];
#pragma unroll
    for (int mi = 0; mi < 2; mi++)
#pragma unroll
        for (int ni = 0; ni < 8; ni++)
#pragma unroll
            for (int j = 0; j < 4; j++) acc[mi][ni][j] = 0.f;

    // prologue load + store stage 0
    ra0 = *(const float4*)(Ag);  ra1 = *(const float4*)(Ag + 4);
    rb0 = *(const float4*)(Bg);  rb1 = *(const float4*)(Bg + 4);
    {
        unsigned* da = &As[lrow*GSTR + lg*8];
        da[0]=f2tf32(ra0.x); da[2]=f2tf32(ra0.y); da[4]=f2tf32(ra0.z); da[6]=f2tf32(ra0.w);
        da[1]=f2tf32(ra1.x); da[3]=f2tf32(ra1.y); da[5]=f2tf32(ra1.z); da[7]=f2tf32(ra1.w);
        unsigned* db = &Bs[lrow*GSTR + lg*8];
        db[0]=f2tf32(rb0.x); db[2]=f2tf32(rb0.y); db[4]=f2tf32(rb0.z); db[6]=f2tf32(rb0.w);
        db[1]=f2tf32(rb1.x); db[3]=f2tf32(rb1.y); db[5]=f2tf32(rb1.z); db[7]=f2tf32(rb1.w);
    }
    __syncthreads();

    const int T = K >> 4;
    for (int t = 0; t < T; t++) {
        const int cur = t & 1;
        if (t + 1 < T) {
            int k0 = (t+1) << 4;
            ra0 = *(const float4*)(Ag + k0);  ra1 = *(const float4*)(Ag + k0 + 4);
            rb0 = *(const float4*)(Bg + k0);  rb1 = *(const float4*)(Bg + k0 + 4);
        }
        const unsigned* Ab = &As[cur*128*GSTR];
        const unsigned* Bb = &Bs[cur*128*GSTR];
#pragma unroll
        for (int ks = 0; ks < 2; ks++) {
            unsigned a[2][4];
#pragma unroll
            for (int mi = 0; mi < 2; mi++) {
                uint2 lo = *(const uint2*)&Ab[(wm + mi*16 + gr)*GSTR + ks*8 + 2*gc];
                uint2 hi = *(const uint2*)&Ab[(wm + mi*16 + 8 + gr)*GSTR + ks*8 + 2*gc];
                a[mi][0] = lo.x; a[mi][1] = hi.x; a[mi][2] = lo.y; a[mi][3] = hi.y;
            }
#pragma unroll
            for (int ni = 0; ni < 8; ni++) {
                uint2 bb = *(const uint2*)&Bb[(wn + ni*8 + gr)*GSTR + ks*8 + 2*gc];
                unsigned b[2] = {bb.x, bb.y};
                mma_tf32(acc[0][ni], a[0], b);
                mma_tf32(acc[1][ni], a[1], b);
            }
        }
        if (t + 1 < T) {
            int nst = (t+1) & 1;
            unsigned* da = &As[nst*128*GSTR + lrow*GSTR + lg*8];
            da[0]=f2tf32(ra0.x); da[2]=f2tf32(ra0.y); da[4]=f2tf32(ra0.z); da[6]=f2tf32(ra0.w);
            da[1]=f2tf32(ra1.x); da[3]=f2tf32(ra1.y); da[5]=f2tf32(ra1.z); da[7]=f2tf32(ra1.w);
            unsigned* db = &Bs[nst*128*GSTR + lrow*GSTR + lg*8];
            db[0]=f2tf32(rb0.x); db[2]=f2tf32(rb0.y); db[4]=f2tf32(rb0.z); db[6]=f2tf32(rb0.w);
            db[1]=f2tf32(rb1.x); db[3]=f2tf32(rb1.y); db[5]=f2tf32(rb1.z); db[7]=f2tf32(rb1.w);
        }
        __syncthreads();
    }

#pragma unroll
    for (int mi = 0; mi < 2; mi++) {
        int m0 = bm + wm + mi*16 + gr;
#pragma unroll
        for (int ni = 0; ni < 8; ni++) {
            int n = bn + wn + ni*8 + 2*gc;
            *(float2*)(C + (size_t)m0 * N + n)       = make_float2(acc[mi][ni][0], acc[mi][ni][1]);
            *(float2*)(C + (size_t)(m0 + 8) * N + n) = make_float2(acc[mi][ni][2], acc[mi][ni][3]);
        }
    }
}

// ---------------- prep ----------------------------------------------------------------
__global__ void prep_kernel(const float* __restrict__ ve, const float* __restrict__ lambdas) {
    int gtid = blockIdx.x * blockDim.x + threadIdx.x;
    int warp = gtid >> 5;
    int lane = gtid & 31;
    if (warp >= B_*S_*NH_) return;
    int h = warp % NH_;
    int s = (warp / NH_) % S_;
    int b = warp / (NH_ * S_);

    const float* row = g_qkv + (size_t)(b*S_ + s) * (3*H_);
    float q1 = row[h*64 + lane],          q2 = row[h*64 + 32 + lane];
    float k1 = row[H_ + h*64 + lane],     k2 = row[H_ + h*64 + 32 + lane];
    float v1 = row[2*H_ + h*64 + lane],   v2 = row[2*H_ + h*64 + 32 + lane];

    float sq = q1*q1 + q2*q2;
    float sk = k1*k1 + k2*k2;
#pragma unroll
    for (int o = 16; o; o >>= 1) {
        sq += __shfl_xor_sync(0xffffffffu, sq, o);
        sk += __shfl_xor_sync(0xffffffffu, sk, o);
    }
    float rq = rsqrtf(sq * (1.f/64.f) + EPS_);
    float rk = rsqrtf(sk * (1.f/64.f) + EPS_);
    q1 *= rq; q2 *= rq; k1 *= rk; k2 *= rk;

    float c  = g_cos[s*32 + lane];
    float sn = g_sin[s*32 + lane];
    float qo1 = q1*c + q2*sn, qo2 = q2*c - q1*sn;
    float ko1 = k1*c + k2*sn, ko2 = k2*c - k1*sn;

    float l0 = lambdas[0], l1 = lambdas[1];
    const float* verow = ve + (size_t)(b*S_ + s) * H_ + h*64;
    float vo1 = l0*v1 + l1*verow[lane];
    float vo2 = l0*v2 + l1*verow[32 + lane];

    size_t o = ((size_t)(b*NH_ + h) * S_ + s) * 64 + lane;
    g_q[o]    = __uint_as_float(f2tf32(qo1));
    g_q[o+32] = __uint_as_float(f2tf32(qo2));
    g_k[o]    = __uint_as_float(f2tf32(ko1));
    g_k[o+32] = __uint_as_float(f2tf32(ko2));
    g_v[o]    = __uint_as_float(f2tf32(vo1));
    g_v[o+32] = __uint_as_float(f2tf32(vo2));
}

// ---------------- flash attention v2 --------------------------------------------------
// BM=128, BN=64, 256 thr = 8 warps; warp w owns q rows [16w,16w+16).
// smem: QP[128][72] (Q pair-permuted, then aliased by P), Ks[64][72] (pair-permuted),
//       Vs[64][72] (natural). Q fragments hoisted to registers before kt loop.
#define FSTR 72
#define FLASH_SMEM_BYTES ((128*FSTR + 64*FSTR + 64*FSTR)*4)   // 73728

__global__ __launch_bounds__(256)
void flash_v2() {
    extern __shared__ float sm[];
    float* QP = sm;                     // 128 x FSTR
    float* Ks = sm + 128*FSTR;          // 64 x FSTR
    float* Vs = Ks + 64*FSTR;           // 64 x FSTR

    const int tid  = threadIdx.x;
    const int lane = tid & 31;
    const int wid  = tid >> 5;
    const int gr   = lane >> 2;
    const int gc   = lane & 3;
    const int qt   = gridDim.x - 1 - blockIdx.x;   // long CTAs first
    const int bh   = blockIdx.y;
    const int arow = wid*16 + gr;

    // --- fill Q (pair-permuted): 2048 float4
    const float* Qg = g_q + ((size_t)bh * S_ + qt*128) * 64;
    for (int i = tid; i < 2048; i += 256) {
        int r = i >> 4, dc = (i & 15) << 2;
        float4 v = *(const float4*)(Qg + r*64 + dc);
        float* dst = &QP[r*FSTR + (dc & ~7) + ((dc & 4) ? 1 : 0)];
        dst[0] = v.x; dst[2] = v.y; dst[4] = v.z; dst[6] = v.w;
    }
    __syncthreads();

    // --- hoist Q fragments (loop-invariant)
    unsigned qa[8][4];
#pragma unroll
    for (int ks = 0; ks < 8; ks++) {
        uint2 lo = *(const uint2*)&QP[arow*FSTR + ks*8 + 2*gc];
        uint2 hi = *(const uint2*)&QP[(arow+8)*FSTR + ks*8 + 2*gc];
        qa[ks][0] = lo.x; qa[ks][1] = hi.x; qa[ks][2] = lo.y; qa[ks][3] = hi.y;
    }

    float o[8][4];
#pragma unroll
    for (int ni = 0; ni < 8; ni++)
#pragma unroll
        for (int j = 0; j < 4; j++) o[ni][j] = 0.f;
    float m0 = -INFINITY, m1 = -INFINITY, l0 = 0.f, l1 = 0.f;

    const int ktmax = 2*qt + 1;
    for (int kt = 0; kt <= ktmax; kt++) {
        __syncthreads();                 // prior P/V/K reads complete (also guards Q hoist)
        const float* Kg = g_k + ((size_t)bh * S_ + kt*64) * 64;
        const float* Vg = g_v + ((size_t)bh * S_ + kt*64) * 64;
        for (int i = tid; i < 1024; i += 256) {
            int r = i >> 4, dc = (i & 15) << 2;
            float4 kv = *(const float4*)(Kg + r*64 + dc);
            float* kd = &Ks[r*FSTR + (dc & ~7) + ((dc & 4) ? 1 : 0)];
            kd[0] = kv.x; kd[2] = kv.y; kd[4] = kv.z; kd[6] = kv.w;
            *(float4*)&Vs[r*FSTR + dc] = *(const float4*)(Vg + r*64 + dc);
        }
        __syncthreads();

        // S = Q K^T
        float sc[8][4];
#pragma unroll
        for (int ni = 0; ni < 8; ni++)
#pragma unroll
            for (int j = 0; j < 4; j++) sc[ni][j] = 0.f;
#pragma unroll
        for (int ks = 0; ks < 8; ks++) {
#pragma unroll
            for (int ni = 0; ni < 8; ni++) {
                uint2 bb = *(const uint2*)&Ks[(ni*8 + gr)*FSTR + ks*8 + 2*gc];
                unsigned b[2] = {bb.x, bb.y};
                mma_tf32(sc[ni], qa[ks], b);
            }
        }

        // scale + causal mask
        const int qrow0 = qt*128 + wid*16 + gr;
        const bool diag = (kt >= 2*qt);
#pragma unroll
        for (int ni = 0; ni < 8; ni++) {
            sc[ni][0] *= 0.125f; sc[ni][1] *= 0.125f;
            sc[ni][2] *= 0.125f; sc[ni][3] *= 0.125f;
            if (diag) {
                int col = kt*64 + ni*8 + 2*gc;
                if (col     > qrow0)     sc[ni][0] = -1e30f;
                if (col + 1 > qrow0)     sc[ni][1] = -1e30f;
                if (col     > qrow0 + 8) sc[ni][2] = -1e30f;
                if (col + 1 > qrow0 + 8) sc[ni][3] = -1e30f;
            }
        }

        // online softmax (rows in 4-lane quads)
        float mx0 = -INFINITY, mx1 = -INFINITY;
#pragma unroll
        for (int ni = 0; ni < 8; ni++) {
            mx0 = fmaxf(mx0, fmaxf(sc[ni][0], sc[ni][1]));
            mx1 = fmaxf(mx1, fmaxf(sc[ni][2], sc[ni][3]));
        }
        mx0 = fmaxf(mx0, __shfl_xor_sync(0xffffffffu, mx0, 1));
        mx0 = fmaxf(mx0, __shfl_xor_sync(0xffffffffu, mx0, 2));
        mx1 = fmaxf(mx1, __shfl_xor_sync(0xffffffffu, mx1, 1));
        mx1 = fmaxf(mx1, __shfl_xor_sync(0xffffffffu, mx1, 2));
        float mn0 = fmaxf(m0, mx0), mn1 = fmaxf(m1, mx1);
        float al0 = __expf(m0 - mn0), al1 = __expf(m1 - mn1);
        m0 = mn0; m1 = mn1;

        // exp + P write (pair-permuted over kv): p at phys col pp, pp+2
        const int pp = (gc < 2) ? 4*gc : 4*gc - 7;
        float* pr0 = &QP[arow*FSTR];
        float* pr1 = &QP[(arow+8)*FSTR];
        float s0 = 0.f, s1 = 0.f;
#pragma unroll
        for (int ni = 0; ni < 8; ni++) {
            float p00 = __expf(sc[ni][0] - mn0);
            float p01 = __expf(sc[ni][1] - mn0);
            float p10 = __expf(sc[ni][2] - mn1);
            float p11 = __expf(sc[ni][3] - mn1);
            s0 += p00 + p01;
            s1 += p10 + p11;
            int c = ni*8 + pp;
            pr0[c]   = __uint_as_float(f2tf32(p00));
            pr0[c+2] = __uint_as_float(f2tf32(p01));
            pr1[c]   = __uint_as_float(f2tf32(p10));
            pr1[c+2] = __uint_as_float(f2tf32(p11));
        }
        s0 += __shfl_xor_sync(0xffffffffu, s0, 1);
        s0 += __shfl_xor_sync(0xffffffffu, s0, 2);
        s1 += __shfl_xor_sync(0xffffffffu, s1, 1);
        s1 += __shfl_xor_sync(0xffffffffu, s1, 2);
        l0 = l0 * al0 + s0;
        l1 = l1 * al1 + s1;

#pragma unroll
        for (int ni = 0; ni < 8; ni++) {
            o[ni][0] *= al0; o[ni][1] *= al0;
            o[ni][2] *= al1; o[ni][3] *= al1;
        }
        __syncwarp();                    // P rows are warp-private

        // O += P V
#pragma unroll
        for (int ks = 0; ks < 8; ks++) {
            uint2 plo = *(const uint2*)&QP[arow*FSTR + ks*8 + 2*gc];
            uint2 phi = *(const uint2*)&QP[(arow+8)*FSTR + ks*8 + 2*gc];
            unsigned pa[4] = {plo.x, phi.x, plo.y, phi.y};
#pragma unroll
            for (int ni = 0; ni < 8; ni++) {
                unsigned b[2];
                b[0] = __float_as_uint(Vs[(ks*8 + gc)*FSTR + ni*8 + gr]);
                b[1] = __float_as_uint(Vs[(ks*8 + gc + 4)*FSTR + ni*8 + gr]);
                mma_tf32(o[ni], pa, b);
            }
        }
    }

    float inv0 = 1.f / l0, inv1 = 1.f / l1;
    const int b = bh / NH_, h = bh % NH_;
    const int srow0 = qt*128 + wid*16 + gr;
#pragma unroll
    for (int ni = 0; ni < 8; ni++) {
        int col = h*64 + ni*8 + 2*gc;
        *(float2*)(g_attn + (size_t)(b*S_ + srow0) * H_ + col) =
            make_float2(o[ni][0]*inv0, o[ni][1]*inv0);
        *(float2*)(g_attn + (size_t)(b*S_ + srow0 + 8) * H_ + col) =
            make_float2(o[ni][2]*inv1, o[ni][3]*inv1);
    }
}

// ---------------- launch --------------------------------------------------------------
extern "C" void kernel_launch(void* const* d_in, const int* in_sizes, int n_in,
                              void* d_out, int out_size) {
    (void)in_sizes; (void)n_in; (void)out_size;
    const float* x       = (const float*)d_in[0];
    const float* ve      = (const float*)d_in[1];
    const float* Wqkv    = (const float*)d_in[2];
    const float* Wo      = (const float*)d_in[3];
    const float* lambdas = (const float*)d_in[4];
    float* out = (float*)d_out;

    void *p_qkv, *p_attn;
    cudaGetSymbolAddress(&p_qkv,  g_qkv);
    cudaGetSymbolAddress(&p_attn, g_attn);

    static bool attr_done = false;
    if (!attr_done) {
        cudaFuncSetAttribute(flash_v2, cudaFuncAttributeMaxDynamicSharedMemorySize,
                             FLASH_SMEM_BYTES);
        cudaFuncSetAttribute(gemm_v2, cudaFuncAttributeMaxDynamicSharedMemorySize,
                             GEMM_SMEM_BYTES);
        attr_done = true;
    }

    // 1) qkv = x @ W_qkv^T   (4096 x 3072 x 1024)
    gemm_v2<<<dim3(3*H_/128, ROWS_/128), 256, GEMM_SMEM_BYTES>>>(x, Wqkv, (float*)p_qkv,
                                                                 ROWS_, 3*H_, H_);
    // 2) RoPE table
    rope_table_kernel<<<(S_*32 + 255)/256, 256>>>();
    // 3) prep
    prep_kernel<<<(B_*S_*NH_*32 + 255)/256, 256>>>(ve, lambdas);
    // 4) causal flash attention
    flash_v2<<<dim3(S_/128, B_*NH_), 256, FLASH_SMEM_BYTES>>>();
    // 5) out = attn @ W_o^T   (4096 x 1024 x 1024)
    gemm_v2<<<dim3(H_/128, ROWS_/128), 256, GEMM_SMEM_BYTES>>>((const float*)p_attn, Wo, out,
                                                               ROWS_, H_, H_);
}